// round 2
// baseline (speedup 1.0000x reference)
#include <cuda_runtime.h>

#define Hh  96
#define Ww  96
#define Dd  48
#define Cc  64
#define HW  (Hh * Ww)        // 9216
#define DHW (Dd * HW)        // 442368

// Scratch: transposed feats [view][h][w][c] and imgs [view][h][w][4]
__device__ float g_feats_t[3 * HW * Cc];   // ~7.08 MB
__device__ float g_imgs_t [3 * HW * 4];    // ~0.44 MB

// ---------------------------------------------------------------------------
// Prepass: (C,H,W) -> (H,W,C) transpose per view via smem tile.
// One block per (view, h) row. Reads and writes both fully coalesced.
// ---------------------------------------------------------------------------
__global__ void __launch_bounds__(256) gridenc_transpose(
    const float* __restrict__ feats,   // (3, 64, 96, 96)
    const float* __restrict__ imgs)    // (3, 3, 96, 96)
{
    int v = blockIdx.x / Hh;
    int h = blockIdx.x % Hh;

    __shared__ float s[Ww * 65];

    const float* fsrc = feats + (size_t)(v * Cc) * HW + h * Ww;
    for (int i = threadIdx.x; i < Cc * Ww; i += 256) {
        int c = i / Ww;
        int w = i - c * Ww;
        s[w * 65 + c] = fsrc[c * HW + w];
    }
    __syncthreads();

    float* fdst = g_feats_t + (size_t)(v * HW + h * Ww) * Cc;
    for (int i = threadIdx.x; i < Ww * Cc; i += 256) {
        int w = i >> 6;
        int c = i & 63;
        fdst[i] = s[w * 65 + c];
    }

    const float* isrc = imgs + (size_t)(v * 3) * HW + h * Ww;
    float* idst = g_imgs_t + (size_t)(v * HW + h * Ww) * 4;
    for (int i = threadIdx.x; i < Ww * 4; i += 256) {
        int w = i >> 2;
        int c = i & 3;
        idst[i] = (c < 3) ? isrc[c * HW + w] : 0.0f;
    }
}

// ---------------------------------------------------------------------------
// Main kernel: one thread per (d, h, w). Computes homography grid, bilinear
// weights + per-corner independently-clamped offsets for views 1,2, then
// writes 73 output channels:
//   0-2  : imgs view0 broadcast
//   3-5  : warped imgs view1
//   6-8  : warped imgs view2
//   9-72 : 3-view feature variance (mask-weighted count)
// ---------------------------------------------------------------------------
__global__ void __launch_bounds__(256) gridenc_main(
    const float* __restrict__ imgs,    // (3, 3, 96, 96) - only view0 used here
    const float* __restrict__ proj,    // (3, 3, 4)
    const float* __restrict__ depth,   // (48,)
    float* __restrict__ out)           // (73, 48, 96, 96)
{
    int pos = blockIdx.x * 256 + threadIdx.x;
    if (pos >= DHW) return;

    int w  = pos % Ww;
    int h  = (pos / Ww) % Hh;
    int d  = pos / HW;
    int hw = h * Ww + w;

    float dep = depth[d];
    float fw = (float)w, fh = (float)h;

    float wts[2][4];
    int   off[2][4];
    float nmask = 1.0f;

#pragma unroll
    for (int vi = 0; vi < 2; ++vi) {
        const float* P = proj + (vi + 1) * 12;
        // pts = R @ [w, h, 1] + T / depth   (matches reference op order)
        float px = P[0] * fw + P[1] * fh + P[2]  + P[3]  / dep;
        float py = P[4] * fw + P[5] * fh + P[6]  + P[7]  / dep;
        float pz = P[8] * fw + P[9] * fh + P[10] + P[11] / dep;
        float xr = px / pz;
        float yr = py / pz;
        float gx = xr / 47.5f - 1.0f;      // (W-1)/2 = 47.5
        float gy = yr / 47.5f - 1.0f;

        nmask += (gx > -1.0f && gx < 1.0f && gy > -1.0f && gy < 1.0f) ? 1.0f : 0.0f;

        float x = (gx + 1.0f) * 0.5f * 95.0f;
        float y = (gy + 1.0f) * 0.5f * 95.0f;

        float x0f = floorf(x), y0f = floorf(y);
        float fx1 = x - x0f, fy1 = y - y0f;
        float fx0 = 1.0f - fx1, fy0 = 1.0f - fy1;

        // per-corner validity (zeros padding) — NaN coords yield all-false
        float vx0 = (x0f >=  0.0f && x0f <= 95.0f) ? 1.0f : 0.0f;
        float vx1 = (x0f >= -1.0f && x0f <= 94.0f) ? 1.0f : 0.0f;
        float vy0 = (y0f >=  0.0f && y0f <= 95.0f) ? 1.0f : 0.0f;
        float vy1 = (y0f >= -1.0f && y0f <= 94.0f) ? 1.0f : 0.0f;

        // per-corner INDEPENDENT clamping (matches reference's per-gather clip)
        int ix0 = (int)fminf(fmaxf(x0f,        0.0f), 95.0f);
        int iy0 = (int)fminf(fmaxf(y0f,        0.0f), 95.0f);
        int ix1 = (int)fminf(fmaxf(x0f + 1.0f, 0.0f), 95.0f);
        int iy1 = (int)fminf(fmaxf(y0f + 1.0f, 0.0f), 95.0f);

        wts[vi][0] = fx0 * fy0 * vx0 * vy0;
        wts[vi][1] = fx1 * fy0 * vx1 * vy0;
        wts[vi][2] = fx0 * fy1 * vx0 * vy1;
        wts[vi][3] = fx1 * fy1 * vx1 * vy1;

        int vb = (vi + 1) * HW;
        off[vi][0] = vb + iy0 * Ww + ix0;
        off[vi][1] = vb + iy0 * Ww + ix1;
        off[vi][2] = vb + iy1 * Ww + ix0;
        off[vi][3] = vb + iy1 * Ww + ix1;
    }

    // channels 0-2: view0 imgs broadcast over depth (coalesced direct reads)
    out[0 * DHW + pos] = imgs[0 * HW + hw];
    out[1 * DHW + pos] = imgs[1 * HW + hw];
    out[2 * DHW + pos] = imgs[2 * HW + hw];

    // channels 3-8: warped imgs, views 1 & 2
#pragma unroll
    for (int vi = 0; vi < 2; ++vi) {
        float ax = 0.0f, ay = 0.0f, az = 0.0f;
#pragma unroll
        for (int k = 0; k < 4; ++k) {
            const float4 t = *(const float4*)(g_imgs_t + (size_t)off[vi][k] * 4);
            float wk = wts[vi][k];
            ax += wk * t.x; ay += wk * t.y; az += wk * t.z;
        }
        out[(3 + 3 * vi + 0) * DHW + pos] = ax;
        out[(3 + 3 * vi + 1) * DHW + pos] = ay;
        out[(3 + 3 * vi + 2) * DHW + pos] = az;
    }

    // channels 9-72: variance over {ref, warp1, warp2}, count = mask_sum
    float inv = 1.0f / nmask;
    const float* refp = g_feats_t + (size_t)hw * Cc;   // view0 at (h,w)

#pragma unroll 4
    for (int cb = 0; cb < Cc; cb += 4) {
        float4 r = *(const float4*)(refp + cb);
        float sx = r.x, sy = r.y, sz = r.z, sw_ = r.w;
        float qx = r.x * r.x, qy = r.y * r.y, qz = r.z * r.z, qw = r.w * r.w;

#pragma unroll
        for (int vi = 0; vi < 2; ++vi) {
            float4 a = *(const float4*)(g_feats_t + (size_t)off[vi][0] * Cc + cb);
            float4 b = *(const float4*)(g_feats_t + (size_t)off[vi][1] * Cc + cb);
            float4 c = *(const float4*)(g_feats_t + (size_t)off[vi][2] * Cc + cb);
            float4 e = *(const float4*)(g_feats_t + (size_t)off[vi][3] * Cc + cb);
            float w0 = wts[vi][0], w1 = wts[vi][1], w2 = wts[vi][2], w3 = wts[vi][3];
            float mx = w0 * a.x + w1 * b.x + w2 * c.x + w3 * e.x;
            float my = w0 * a.y + w1 * b.y + w2 * c.y + w3 * e.y;
            float mz = w0 * a.z + w1 * b.z + w2 * c.z + w3 * e.z;
            float mw = w0 * a.w + w1 * b.w + w2 * c.w + w3 * e.w;
            sx += mx; sy += my; sz += mz; sw_ += mw;
            qx += mx * mx; qy += my * my; qz += mz * mz; qw += mw * mw;
        }
        float mx = sx * inv, my = sy * inv, mz = sz * inv, mw = sw_ * inv;
        out[(9 + cb + 0) * DHW + pos] = qx * inv - mx * mx;
        out[(9 + cb + 1) * DHW + pos] = qy * inv - my * my;
        out[(9 + cb + 2) * DHW + pos] = qz * inv - mz * mz;
        out[(9 + cb + 3) * DHW + pos] = qw * inv - mw * mw;
    }
}

// ---------------------------------------------------------------------------
// kernel_launch: graph-capturable, allocation-free.
// Inputs identified robustly by element count (all distinct):
//   imgs (1,3,3,96,96)=82944; feats (1,3,64,96,96)=1769472;
//   proj_mats (1,3,3,4)=36; depth_values (1,48)=48.
// d_out: (1,73,48,96,96) f32.
// ---------------------------------------------------------------------------
extern "C" void kernel_launch(void* const* d_in, const int* in_sizes, int n_in,
                              void* d_out, int out_size)
{
    const float* imgs  = nullptr;
    const float* feats = nullptr;
    const float* proj  = nullptr;
    const float* depth = nullptr;
    for (int i = 0; i < n_in; ++i) {
        switch (in_sizes[i]) {
            case 3 * 3 * HW:  imgs  = (const float*)d_in[i]; break;
            case 3 * Cc * HW: feats = (const float*)d_in[i]; break;
            case 36:          proj  = (const float*)d_in[i]; break;
            case Dd:          depth = (const float*)d_in[i]; break;
        }
    }
    float* out = (float*)d_out;

    gridenc_transpose<<<3 * Hh, 256>>>(feats, imgs);
    gridenc_main<<<DHW / 256, 256>>>(imgs, proj, depth, out);
}

// round 3
// speedup vs baseline: 1.7275x; 1.7275x over previous
#include <cuda_runtime.h>

#define Hh  96
#define Ww  96
#define Dd  48
#define Cc  64
#define HW  (Hh * Ww)        // 9216
#define DHW (Dd * HW)        // 442368
#define P   32               // positions per block (divides Ww)

// Scratch: transposed feats [view][h][w][c] and imgs [view][h][w][4]
__device__ float g_feats_t[3 * HW * Cc];   // ~7.08 MB
__device__ float g_imgs_t [3 * HW * 4];    // ~0.44 MB

// ---------------------------------------------------------------------------
// Prepass: (C,H,W) -> (H,W,C) transpose per view via smem tile.
// ---------------------------------------------------------------------------
__global__ void __launch_bounds__(256) gridenc_transpose(
    const float* __restrict__ feats,   // (3, 64, 96, 96)
    const float* __restrict__ imgs)    // (3, 3, 96, 96)
{
    int v = blockIdx.x / Hh;
    int h = blockIdx.x % Hh;

    __shared__ float s[Ww * 65];

    const float* fsrc = feats + (size_t)(v * Cc) * HW + h * Ww;
    for (int i = threadIdx.x; i < Cc * Ww; i += 256) {
        int c = i / Ww;
        int w = i - c * Ww;
        s[w * 65 + c] = fsrc[c * HW + w];
    }
    __syncthreads();

    float* fdst = g_feats_t + (size_t)(v * HW + h * Ww) * Cc;
    for (int i = threadIdx.x; i < Ww * Cc; i += 256) {
        int w = i >> 6;
        int c = i & 63;
        fdst[i] = s[w * 65 + c];
    }

    const float* isrc = imgs + (size_t)(v * 3) * HW + h * Ww;
    float* idst = g_imgs_t + (size_t)(v * HW + h * Ww) * 4;
    for (int i = threadIdx.x; i < Ww * 4; i += 256) {
        int w = i >> 2;
        int c = i & 3;
        idst[i] = (c < 3) ? isrc[c * HW + w] : 0.0f;
    }
}

// ---------------------------------------------------------------------------
// Main kernel. Block = 32 consecutive positions within one (d,h) row.
// Phase 1 (warp 0): grid math -> smem wts/off/inv/hw; img channels 0-8.
// Phase 2 (256 thr): thread = (position, 4-channel group). Gathers are lane-
//                    dense in the channel dim (coalesced 256B per corner).
//                    Variance written to smem tile s_var[c][p].
// Phase 3 (256 thr): coalesced stores of the 64 variance channels.
// ---------------------------------------------------------------------------
__global__ void __launch_bounds__(256) gridenc_main(
    const float* __restrict__ imgs,    // (3, 3, 96, 96) - only view0 used
    const float* __restrict__ proj,    // (3, 3, 4)
    const float* __restrict__ depth,   // (48,)
    float* __restrict__ out)           // (73, 48, 96, 96)
{
    __shared__ float s_wts[2][4][P];
    __shared__ int   s_off[2][4][P];
    __shared__ float s_inv[P];
    __shared__ int   s_hw [P];
    __shared__ float s_var[Cc][P + 1];   // pad -> conflict-free column reads

    const int tid  = threadIdx.x;
    const int pos0 = blockIdx.x * P;

    // ---------------- Phase 1: one warp, one position per lane -------------
    if (tid < P) {
        int pos = pos0 + tid;
        int w   = pos % Ww;
        int h   = (pos / Ww) % Hh;
        int d   = pos / HW;
        int hw  = h * Ww + w;
        s_hw[tid] = hw;

        float dep = depth[d];
        float fw = (float)w, fh = (float)h;
        float nmask = 1.0f;

#pragma unroll
        for (int vi = 0; vi < 2; ++vi) {
            const float* Pm = proj + (vi + 1) * 12;
            float px = Pm[0] * fw + Pm[1] * fh + Pm[2]  + Pm[3]  / dep;
            float py = Pm[4] * fw + Pm[5] * fh + Pm[6]  + Pm[7]  / dep;
            float pz = Pm[8] * fw + Pm[9] * fh + Pm[10] + Pm[11] / dep;
            float gx = (px / pz) / 47.5f - 1.0f;
            float gy = (py / pz) / 47.5f - 1.0f;

            nmask += (gx > -1.0f && gx < 1.0f && gy > -1.0f && gy < 1.0f) ? 1.0f : 0.0f;

            float x = (gx + 1.0f) * 0.5f * 95.0f;
            float y = (gy + 1.0f) * 0.5f * 95.0f;

            float x0f = floorf(x), y0f = floorf(y);
            float fx1 = x - x0f, fy1 = y - y0f;
            float fx0 = 1.0f - fx1, fy0 = 1.0f - fy1;

            // per-corner validity (zeros padding); NaN coords -> all-false
            float vx0 = (x0f >=  0.0f && x0f <= 95.0f) ? 1.0f : 0.0f;
            float vx1 = (x0f >= -1.0f && x0f <= 94.0f) ? 1.0f : 0.0f;
            float vy0 = (y0f >=  0.0f && y0f <= 95.0f) ? 1.0f : 0.0f;
            float vy1 = (y0f >= -1.0f && y0f <= 94.0f) ? 1.0f : 0.0f;

            // per-corner INDEPENDENT clamping (matches reference)
            int ix0 = (int)fminf(fmaxf(x0f,        0.0f), 95.0f);
            int iy0 = (int)fminf(fmaxf(y0f,        0.0f), 95.0f);
            int ix1 = (int)fminf(fmaxf(x0f + 1.0f, 0.0f), 95.0f);
            int iy1 = (int)fminf(fmaxf(y0f + 1.0f, 0.0f), 95.0f);

            float w0 = fx0 * fy0 * vx0 * vy0;
            float w1 = fx1 * fy0 * vx1 * vy0;
            float w2 = fx0 * fy1 * vx0 * vy1;
            float w3 = fx1 * fy1 * vx1 * vy1;

            s_wts[vi][0][tid] = w0;
            s_wts[vi][1][tid] = w1;
            s_wts[vi][2][tid] = w2;
            s_wts[vi][3][tid] = w3;

            int vb = (vi + 1) * HW;
            int o0 = vb + iy0 * Ww + ix0;
            int o1 = vb + iy0 * Ww + ix1;
            int o2 = vb + iy1 * Ww + ix0;
            int o3 = vb + iy1 * Ww + ix1;
            s_off[vi][0][tid] = o0;
            s_off[vi][1][tid] = o1;
            s_off[vi][2][tid] = o2;
            s_off[vi][3][tid] = o3;

            // warped img channels (3 floats) for this view
            float4 t0 = *(const float4*)(g_imgs_t + (size_t)o0 * 4);
            float4 t1 = *(const float4*)(g_imgs_t + (size_t)o1 * 4);
            float4 t2 = *(const float4*)(g_imgs_t + (size_t)o2 * 4);
            float4 t3 = *(const float4*)(g_imgs_t + (size_t)o3 * 4);
            float ax = w0 * t0.x + w1 * t1.x + w2 * t2.x + w3 * t3.x;
            float ay = w0 * t0.y + w1 * t1.y + w2 * t2.y + w3 * t3.y;
            float az = w0 * t0.z + w1 * t1.z + w2 * t2.z + w3 * t3.z;
            out[(3 + 3 * vi + 0) * DHW + pos] = ax;
            out[(3 + 3 * vi + 1) * DHW + pos] = ay;
            out[(3 + 3 * vi + 2) * DHW + pos] = az;
        }

        s_inv[tid] = 1.0f / nmask;

        // channels 0-2: view0 imgs broadcast over depth
        out[0 * DHW + pos] = imgs[0 * HW + hw];
        out[1 * DHW + pos] = imgs[1 * HW + hw];
        out[2 * DHW + pos] = imgs[2 * HW + hw];
    }
    __syncthreads();

    // ---------------- Phase 2: dense channel gathers ------------------------
    // thread -> (position p, channel group c4); 16 positions per pass, 2 passes
    {
        const int c4 = tid & 15;        // channels c4*4 .. c4*4+3
        const int pl = tid >> 4;        // 0..15

#pragma unroll
        for (int pass = 0; pass < 2; ++pass) {
            int p  = pass * 16 + pl;
            int hw = s_hw[p];

            float4 r = *(const float4*)(g_feats_t + (size_t)hw * Cc + c4 * 4);
            float sx = r.x, sy = r.y, sz = r.z, sw_ = r.w;
            float qx = r.x * r.x, qy = r.y * r.y, qz = r.z * r.z, qw = r.w * r.w;

#pragma unroll
            for (int vi = 0; vi < 2; ++vi) {
                float w0 = s_wts[vi][0][p], w1 = s_wts[vi][1][p];
                float w2 = s_wts[vi][2][p], w3 = s_wts[vi][3][p];
                float4 a = *(const float4*)(g_feats_t + (size_t)s_off[vi][0][p] * Cc + c4 * 4);
                float4 b = *(const float4*)(g_feats_t + (size_t)s_off[vi][1][p] * Cc + c4 * 4);
                float4 c = *(const float4*)(g_feats_t + (size_t)s_off[vi][2][p] * Cc + c4 * 4);
                float4 e = *(const float4*)(g_feats_t + (size_t)s_off[vi][3][p] * Cc + c4 * 4);
                float mx = w0 * a.x + w1 * b.x + w2 * c.x + w3 * e.x;
                float my = w0 * a.y + w1 * b.y + w2 * c.y + w3 * e.y;
                float mz = w0 * a.z + w1 * b.z + w2 * c.z + w3 * e.z;
                float mw = w0 * a.w + w1 * b.w + w2 * c.w + w3 * e.w;
                sx += mx; sy += my; sz += mz; sw_ += mw;
                qx += mx * mx; qy += my * my; qz += mz * mz; qw += mw * mw;
            }

            float inv = s_inv[p];
            float mx = sx * inv, my = sy * inv, mz = sz * inv, mw = sw_ * inv;
            s_var[c4 * 4 + 0][p] = qx * inv - mx * mx;
            s_var[c4 * 4 + 1][p] = qy * inv - my * my;
            s_var[c4 * 4 + 2][p] = qz * inv - mz * mz;
            s_var[c4 * 4 + 3][p] = qw * inv - mw * mw;
        }
    }
    __syncthreads();

    // ---------------- Phase 3: coalesced variance stores --------------------
    {
        const int p  = tid & 31;
        const int cw = tid >> 5;        // warp id = channel offset
#pragma unroll
        for (int it = 0; it < 8; ++it) {
            int c = it * 8 + cw;
            out[(9 + c) * DHW + pos0 + p] = s_var[c][p];
        }
    }
}

// ---------------------------------------------------------------------------
// kernel_launch: graph-capturable, allocation-free.
// Inputs identified by element count (all distinct):
//   imgs=82944; feats=1769472; proj_mats=36; depth_values=48.
// ---------------------------------------------------------------------------
extern "C" void kernel_launch(void* const* d_in, const int* in_sizes, int n_in,
                              void* d_out, int out_size)
{
    const float* imgs  = nullptr;
    const float* feats = nullptr;
    const float* proj  = nullptr;
    const float* depth = nullptr;
    for (int i = 0; i < n_in; ++i) {
        switch (in_sizes[i]) {
            case 3 * 3 * HW:  imgs  = (const float*)d_in[i]; break;
            case 3 * Cc * HW: feats = (const float*)d_in[i]; break;
            case 36:          proj  = (const float*)d_in[i]; break;
            case Dd:          depth = (const float*)d_in[i]; break;
        }
    }
    float* out = (float*)d_out;

    gridenc_transpose<<<3 * Hh, 256>>>(feats, imgs);
    gridenc_main<<<DHW / P, 256>>>(imgs, proj, depth, out);
}